// round 15
// baseline (speedup 1.0000x reference)
#include <cuda_runtime.h>
#include <math.h>
#include <stdint.h>

#define NB   512
#define C0   256
#define M    80
#define PIX  676      // 26*26
#define CHUNK 8
#define PTILE 420     // 15 packed rows * 28 cols (padded pair entries per channel)
#define ITILE 338     // 13 * 26 interior pair entries per channel

typedef unsigned long long ull;

// Data tensors (packed-pair layouts)
__device__ float2 g_y2 [512u*256u*420u];       // deconv out, padded-pair layout
__device__ float2 g_xp2[512u*80u*338u];        // preproc "x", interior pairs
__device__ float2 g_h2 [512u*80u*338u];        // hidden state, interior pairs
__device__ float2 g_g2p[512u*80u*338u];        // sigmoid(u2.ns1+b2), interior pairs
__device__ ulonglong2 g_hg2[512u*80u*210u];    // h*g1, padded pairs [15][28]
__device__ ulonglong2 g_ns2[512u*80u*210u];    // ns1,  padded pairs [15][28]

// Pre-duplicated weights — accessed ONLY from device code (never passed from host)
__device__ ull g_wpre[10u*32u*640u];           // preproc  (MT=10, NCH=32, CHUNK=8)
__device__ ull g_winh[10u*10u*640u];           // w_inh    (MT=10, NCH=10)
__device__ ull g_wexc[10u*10u*640u];           // w_exc
__device__ ull g_wu1 [5u*10u*128u];            // u1 gate  (MT=5, NCH=10, 16ml x 8c)
__device__ ull g_wu2 [5u*10u*128u];            // u2 gate

__device__ __forceinline__ float sigm_(float v) { return 1.f / (1.f + expf(-v)); }
__device__ __forceinline__ float sftp_(float v) { return fmaxf(v, 0.f) + log1pf(expf(-fabsf(v))); }

__device__ __forceinline__ ull pk2(float lo, float hi) {
    ull r; asm("mov.b64 %0, {%1, %2};" : "=l"(r) : "f"(lo), "f"(hi)); return r;
}
__device__ __forceinline__ void upk2(ull v, float& lo, float& hi) {
    asm("mov.b64 {%0, %1}, %2;" : "=f"(lo), "=f"(hi) : "l"(v));
}
__device__ __forceinline__ ull fma2(ull a, ull b, ull c) {
    ull d; asm("fma.rn.f32x2 %0, %1, %2, %3;" : "=l"(d) : "l"(a), "l"(b), "l"(c)); return d;
}
__device__ __forceinline__ void cpa16(void* s, const void* g) {
    uint32_t sa = (uint32_t)__cvta_generic_to_shared(s);
    asm volatile("cp.async.cg.shared.global [%0], [%1], 16;" :: "r"(sa), "l"(g));
}
__device__ __forceinline__ void cpa_commit() {
    asm volatile("cp.async.commit_group;" ::: "memory");
}
__device__ __forceinline__ void cpa_wait1() {
    asm volatile("cp.async.wait_group 1;" ::: "memory");
}
__device__ __forceinline__ void cpa_wait0() {
    asm volatile("cp.async.wait_group 0;" ::: "memory");
}

// ---------------------------------------------------------------------------
// Weight prep. Conv layout per (mt,ch): [(ml*8 + c)*10 + slot], slot 9 zero.
// Gate layout per (mt,ch): [ml*8 + c].
// ---------------------------------------------------------------------------
template<int SEL>   // 0 = preproc, 1 = inh, 2 = exc
__global__ void k_wprep_conv(const float* __restrict__ w, int NCH, int CIN, int total)
{
    ull* dst = (SEL == 0) ? g_wpre : (SEL == 1) ? g_winh : g_wexc;
    int idx = blockIdx.x*256 + threadIdx.x;
    if (idx >= total) return;
    int slot = idx % 10; int q = idx / 10;
    int c = q % 8; q /= 8;
    int ml = q % 8; q /= 8;
    int ch = q % NCH; int mt = q / NCH;
    ull v = 0ull;
    if (slot < 9) {
        float wv = w[((mt*8 + ml)*CIN + ch*8 + c)*9 + slot];
        v = pk2(wv, wv);
    }
    dst[idx] = v;
}

template<int G>     // 0 = u1, 1 = u2
__global__ void k_wprep_gate(const float* __restrict__ uw)
{
    ull* dst = G ? g_wu2 : g_wu1;
    int idx = blockIdx.x*256 + threadIdx.x;
    if (idx >= 5*10*128) return;
    int c = idx % 8; int q = idx / 8;
    int ml = q % 16; q /= 16;
    int ch = q % 10; int mt = q / 10;
    float wv = uw[(mt*16 + ml)*M + ch*8 + c];
    dst[idx] = pk2(wv, wv);
}

// ---------------------------------------------------------------------------
// Deconv 2x2 / stride 2; writes packed-pair layout g_y2 (rows 13/14 dup'd).
// ---------------------------------------------------------------------------
__global__ __launch_bounds__(256) void k_deconv(const float* __restrict__ x,
                                                const float4* __restrict__ dw4,
                                                const float* __restrict__ db)
{
    __shared__ ull xs[8][256];
    const int n = blockIdx.y;
    const int pid0 = blockIdx.x * 8;
    const int tid = threadIdx.x;

    #pragma unroll
    for (int g = 0; g < 8; g++) {
        int pid = pid0 + g;
        float v = (pid < 196) ? x[(n*256 + tid)*196 + pid] : 0.f;
        xs[g][tid] = pk2(v, v);
    }
    __syncthreads();

    ull acc0[8], acc1[8];
    #pragma unroll
    for (int g = 0; g < 8; g++) { acc0[g] = 0ull; acc1[g] = 0ull; }

    for (int ch = 0; ch < 256; ch++) {
        float4 w = dw4[ch*256 + tid];
        ull w01 = pk2(w.x, w.y);
        ull w23 = pk2(w.z, w.w);
        #pragma unroll
        for (int g = 0; g < 8; g++) {
            ull xv = xs[g][ch];
            acc0[g] = fma2(xv, w01, acc0[g]);
            acc1[g] = fma2(xv, w23, acc1[g]);
        }
    }

    const float b = db[tid];
    float2* yc = g_y2 + (ull)(n*256 + tid)*PTILE;
    #pragma unroll
    for (int g = 0; g < 8; g++) {
        int pid = pid0 + g;
        if (pid < 196) {
            int i = pid / 14, j = pid % 14;
            float a0,a1,a2,a3; upk2(acc0[g],a0,a1); upk2(acc1[g],a2,a3);
            a0 += b; a1 += b; a2 += b; a3 += b;
            int ry0 = 2*i, ry1 = 2*i + 1, col0 = 2*j, col1 = 2*j + 1;
            if (ry0 <= 14) {
                ((float*)&yc[ry0*28 + col0])[0] = a0;
                ((float*)&yc[ry0*28 + col1])[0] = a1;
            }
            if (ry0 >= 13) {
                ((float*)&yc[(ry0-13)*28 + col0])[1] = a0;
                ((float*)&yc[(ry0-13)*28 + col1])[1] = a1;
            }
            if (ry1 <= 14) {
                ((float*)&yc[ry1*28 + col0])[0] = a2;
                ((float*)&yc[ry1*28 + col1])[0] = a3;
            }
            if (ry1 >= 13) {
                ((float*)&yc[(ry1-13)*28 + col0])[1] = a2;
                ((float*)&yc[(ry1-13)*28 + col1])[1] = a3;
            }
        }
    }
}

// ---------------------------------------------------------------------------
// Blocked 1x1 gates, DOUBLE-BUFFERED (CHUNK=8, 10 chunks).
// G=0: gate1 (src g_h2; out g_hg2 padded incl. dup halo).
// G=1: gate2 (src g_ns2 padded; out g_g2p interior).
// ---------------------------------------------------------------------------
template<int G>
__global__ __launch_bounds__(192, 3) void k_gatec(const float* __restrict__ ub)
{
    constexpr int IN = G ? PTILE : ITILE;   // float2 entries per channel
    constexpr int S2 = IN / 2;              // ulonglong2 per channel
    const ull* wp = G ? g_wu2 : g_wu1;
    extern __shared__ float sm[];
    float2* sIn = (float2*)sm;                     // 2 * CHUNK * IN
    ull*    sW  = (ull*)(sIn + 2*CHUNK*IN);        // 2 * 128

    const int n = blockIdx.y, mt = blockIdx.x, tid = threadIdx.x;
    const bool act = tid < 169;
    const int py  = act ? tid / 13 : 0;
    const int px0 = act ? (tid % 13) * 2 : 0;
    const int e0  = py*26 + px0;
    const int ep  = (py+1)*28 + px0 + 1;

    const ulonglong2* srcBase = G
        ? (const ulonglong2*)((const float2*)g_ns2 + (ull)(n*M)*PTILE)
        : (const ulonglong2*)(g_h2 + (ull)(n*M)*ITILE);

    ull acc[16][2];
    #pragma unroll
    for (int ml = 0; ml < 16; ml++) { acc[ml][0] = 0ull; acc[ml][1] = 0ull; }

    // stage chunk 0 into buffer 0
    {
        ulonglong2* di = (ulonglong2*)sIn;
        for (int idx = tid; idx < CHUNK*S2; idx += 192) cpa16(di + idx, srcBase + idx);
        const ulonglong2* ws = (const ulonglong2*)(wp + (ull)(mt*10)*128);
        ulonglong2* dw = (ulonglong2*)sW;
        if (tid < 64) cpa16(dw + tid, ws + tid);
        cpa_commit();
    }

    for (int ch = 0; ch < 10; ch++) {
        if (ch + 1 < 10) {
            const int buf = (ch + 1) & 1;
            const ulonglong2* src = srcBase + (ull)(ch+1)*CHUNK*S2;
            ulonglong2* di = (ulonglong2*)(sIn + buf*CHUNK*IN);
            for (int idx = tid; idx < CHUNK*S2; idx += 192) cpa16(di + idx, src + idx);
            const ulonglong2* ws = (const ulonglong2*)(wp + (ull)(mt*10 + ch+1)*128);
            ulonglong2* dw = (ulonglong2*)(sW + buf*128);
            if (tid < 64) cpa16(dw + tid, ws + tid);
            cpa_commit();
            cpa_wait1();
        } else cpa_wait0();
        __syncthreads();

        const float2* bIn = sIn + (ch & 1)*CHUNK*IN;
        const ull*    bW  = sW  + (ch & 1)*128;
        #pragma unroll 1
        for (int c = 0; c < CHUNK; c++) {
            ull P0, P1;
            if (G) {
                const ull* s = (const ull*)(bIn + c*PTILE + ep);
                P0 = s[0]; P1 = s[1];
            } else {
                ulonglong2 v = *(const ulonglong2*)(bIn + c*ITILE + e0);
                P0 = v.x; P1 = v.y;
            }
            #pragma unroll
            for (int ml = 0; ml < 16; ml++) {
                ull wv = bW[ml*CHUNK + c];
                acc[ml][0] = fma2(P0, wv, acc[ml][0]);
                acc[ml][1] = fma2(P1, wv, acc[ml][1]);
            }
        }
        __syncthreads();
    }

    if (!act) return;

    #pragma unroll
    for (int ml = 0; ml < 16; ml++) {
        const int m = mt*16 + ml;
        const float b = ub[m];
        float t0,b0,t1,b1;
        upk2(acc[ml][0], t0, b0);
        upk2(acc[ml][1], t1, b1);
        if (G) {
            *(float4*)(g_g2p + (ull)(n*M + m)*ITILE + e0) =
                make_float4(sigm_(t0+b), sigm_(b0+b), sigm_(t1+b), sigm_(b1+b));
        } else {
            float4 hv = *(const float4*)(g_h2 + (ull)(n*M + m)*ITILE + e0);
            float vt0 = hv.x * sigm_(t0+b);
            float vb0 = hv.y * sigm_(b0+b);
            float vt1 = hv.z * sigm_(t1+b);
            float vb1 = hv.w * sigm_(b1+b);
            float2* chan = (float2*)g_hg2 + (ull)(n*M + m)*PTILE;
            float2* dst = chan + ep;
            dst[0] = make_float2(vt0, vb0);
            dst[1] = make_float2(vt1, vb1);
            if (py == 12) {                         // img row 12 -> (0,col).y
                ((float*)(chan + px0+1))[1] = vt0;
                ((float*)(chan + px0+2))[1] = vt1;
            }
            if (py == 0) {                          // img row 13 -> (14,col).x
                ((float*)(chan + 14*28 + px0+1))[0] = vb0;
                ((float*)(chan + 14*28 + px0+2))[0] = vb1;
            }
        }
    }
}

// ---------------------------------------------------------------------------
// Unified 3x3 conv, DOUBLE-BUFFERED (CHUNK=8).
//   EPI 0: preproc (src g_y2 packed; out g_xp2 + bias, g_h2 = 0,
//                   g_ns2 = softplus incl. dup halo -- fused t=0 init)
//   EPI 1: inh     (src g_hg2; out g_ns2 padded incl. dup halo)
//   EPI 2: exc -> g_h2  (GRU blend with g_g2p)
//   EPI 3: exc -> out (unpacked)
// ---------------------------------------------------------------------------
template<int CIN, int EPI>
__global__ __launch_bounds__(192, 3) void k_conv(const float* __restrict__ p0,
                                                 const float* __restrict__ p1,
                                                 float* __restrict__ out)
{
    constexpr int NCH = CIN / CHUNK;
    const ull* wp = (EPI == 0) ? g_wpre : (EPI == 1) ? g_winh : g_wexc;
    extern __shared__ float sm[];
    float2* sIn2 = (float2*)sm;                        // 2 * CHUNK*PTILE
    ull*    sWp  = (ull*)(sIn2 + 2*CHUNK*PTILE);       // 2 * 640

    const int n = blockIdx.y, mt = blockIdx.x, tid = threadIdx.x;
    const bool act = tid < 169;
    const int py  = act ? tid / 13 : 0;
    const int px0 = act ? (tid % 13) * 2 : 0;
    const int e0  = py*26 + px0;

    const ulonglong2* srcBase;
    if (EPI == 0)      srcBase = (const ulonglong2*)(g_y2 + (ull)(n*C0)*PTILE);
    else if (EPI == 1) srcBase = (const ulonglong2*)((const float2*)g_hg2 + (ull)(n*M)*PTILE);
    else               srcBase = (const ulonglong2*)((const float2*)g_ns2 + (ull)(n*M)*PTILE);

    ull acc[8][2];
    #pragma unroll
    for (int ml = 0; ml < 8; ml++) { acc[ml][0]=0ull; acc[ml][1]=0ull; }

    // stage chunk 0 into buffer 0
    {
        ulonglong2* di = (ulonglong2*)sIn2;
        for (int idx = tid; idx < CHUNK*210; idx += 192) cpa16(di + idx, srcBase + idx);
        const ulonglong2* ws = (const ulonglong2*)(wp + (ull)(mt*NCH)*640);
        ulonglong2* dw = (ulonglong2*)sWp;
        for (int idx = tid; idx < 320; idx += 192) cpa16(dw + idx, ws + idx);
        cpa_commit();
    }

    for (int ch = 0; ch < NCH; ch++) {
        if (ch + 1 < NCH) {
            const int buf = (ch + 1) & 1;
            const ulonglong2* src = srcBase + (ull)(ch+1)*CHUNK*210;
            ulonglong2* di = (ulonglong2*)(sIn2 + buf*CHUNK*PTILE);
            for (int idx = tid; idx < CHUNK*210; idx += 192) cpa16(di + idx, src + idx);
            const ulonglong2* ws = (const ulonglong2*)(wp + (ull)(mt*NCH + ch+1)*640);
            ulonglong2* dw = (ulonglong2*)(sWp + buf*640);
            for (int idx = tid; idx < 320; idx += 192) cpa16(dw + idx, ws + idx);
            cpa_commit();
            cpa_wait1();
        } else cpa_wait0();
        __syncthreads();

        const float2* bIn = sIn2 + (ch & 1)*CHUNK*PTILE;
        const ull*    bW  = sWp  + (ch & 1)*640;
        #pragma unroll 1
        for (int c = 0; c < CHUNK; c++) {
            ull P[3][4];
            const float2* base = bIn + c*PTILE + py*28 + px0;
            #pragma unroll
            for (int r = 0; r < 3; r++) {
                const ulonglong2* rp = (const ulonglong2*)(base + r*28);
                ulonglong2 A = rp[0], B = rp[1];
                P[r][0] = A.x; P[r][1] = A.y; P[r][2] = B.x; P[r][3] = B.y;
            }
            #pragma unroll
            for (int ml = 0; ml < 8; ml++) {
                const ulonglong2* wp2 = (const ulonglong2*)(bW + (ml*CHUNK + c)*10);
                ulonglong2 W01 = wp2[0], W23 = wp2[1];
                acc[ml][0] = fma2(P[0][0], W01.x, acc[ml][0]);
                acc[ml][1] = fma2(P[0][1], W01.x, acc[ml][1]);
                acc[ml][0] = fma2(P[0][1], W01.y, acc[ml][0]);
                acc[ml][1] = fma2(P[0][2], W01.y, acc[ml][1]);
                acc[ml][0] = fma2(P[0][2], W23.x, acc[ml][0]);
                acc[ml][1] = fma2(P[0][3], W23.x, acc[ml][1]);
                acc[ml][0] = fma2(P[1][0], W23.y, acc[ml][0]);
                acc[ml][1] = fma2(P[1][1], W23.y, acc[ml][1]);
                ulonglong2 W45 = wp2[2], W67 = wp2[3];
                acc[ml][0] = fma2(P[1][1], W45.x, acc[ml][0]);
                acc[ml][1] = fma2(P[1][2], W45.x, acc[ml][1]);
                acc[ml][0] = fma2(P[1][2], W45.y, acc[ml][0]);
                acc[ml][1] = fma2(P[1][3], W45.y, acc[ml][1]);
                acc[ml][0] = fma2(P[2][0], W67.x, acc[ml][0]);
                acc[ml][1] = fma2(P[2][1], W67.x, acc[ml][1]);
                acc[ml][0] = fma2(P[2][1], W67.y, acc[ml][0]);
                acc[ml][1] = fma2(P[2][2], W67.y, acc[ml][1]);
                ull W8 = ((const ull*)wp2)[8];
                acc[ml][0] = fma2(P[2][2], W8, acc[ml][0]);
                acc[ml][1] = fma2(P[2][3], W8, acc[ml][1]);
            }
        }
        __syncthreads();
    }

    if (!act) return;

    #pragma unroll
    for (int ml = 0; ml < 8; ml++) {
        const int m = mt*8 + ml;
        const ull b338 = (ull)(n*M + m)*ITILE;
        float t0,b0,t1,b1;
        upk2(acc[ml][0], t0, b0);
        upk2(acc[ml][1], t1, b1);

        if (EPI == 0) {
            float b = p0[m];
            float xt0 = t0+b, xb0 = b0+b, xt1 = t1+b, xb1 = b1+b;
            *(float4*)(g_xp2 + b338 + e0) = make_float4(xt0, xb0, xt1, xb1);
            *(float4*)(g_h2  + b338 + e0) = make_float4(0.f, 0.f, 0.f, 0.f);
            float nt0 = sftp_(xt0), nb0 = sftp_(xb0), nt1 = sftp_(xt1), nb1 = sftp_(xb1);
            float2* chan = (float2*)g_ns2 + (ull)(n*M + m)*PTILE;
            float2* dst = chan + (py+1)*28 + px0 + 1;
            dst[0] = make_float2(nt0, nb0);
            dst[1] = make_float2(nt1, nb1);
            if (py == 12) {
                ((float*)(chan + px0+1))[1] = nt0;
                ((float*)(chan + px0+2))[1] = nt1;
            }
            if (py == 0) {
                ((float*)(chan + 14*28 + px0+1))[0] = nb0;
                ((float*)(chan + 14*28 + px0+2))[0] = nb1;
            }
        } else if (EPI == 1) {
            float al = p0[m], mm = p1[m];
            float4 xv = *(const float4*)(g_xp2 + b338 + e0);
            float4 hv = *(const float4*)(g_h2  + b338 + e0);
            float nt0 = sftp_(xv.x - t0*(al*hv.x + mm));
            float nb0 = sftp_(xv.y - b0*(al*hv.y + mm));
            float nt1 = sftp_(xv.z - t1*(al*hv.z + mm));
            float nb1 = sftp_(xv.w - b1*(al*hv.w + mm));
            float2* chan = (float2*)g_ns2 + (ull)(n*M + m)*PTILE;
            float2* dst = chan + (py+1)*28 + px0 + 1;
            dst[0] = make_float2(nt0, nb0);
            dst[1] = make_float2(nt1, nb1);
            if (py == 12) {
                ((float*)(chan + px0+1))[1] = nt0;
                ((float*)(chan + px0+2))[1] = nt1;
            }
            if (py == 0) {
                ((float*)(chan + 14*28 + px0+1))[0] = nb0;
                ((float*)(chan + 14*28 + px0+2))[0] = nb1;
            }
        } else {
            float4 gv = *(const float4*)(g_g2p + b338 + e0);
            float4 hv = *(const float4*)(g_h2  + b338 + e0);
            float hn0 = (1.f - gv.x)*hv.x + gv.x*sftp_(t0);
            float hn1 = (1.f - gv.y)*hv.y + gv.y*sftp_(b0);
            float hn2 = (1.f - gv.z)*hv.z + gv.z*sftp_(t1);
            float hn3 = (1.f - gv.w)*hv.w + gv.w*sftp_(b1);
            if (EPI == 2) {
                *(float4*)(g_h2 + b338 + e0) = make_float4(hn0, hn1, hn2, hn3);
            } else {
                const int it = (n*M + m)*PIX + e0;
                *(float2*)&out[it]       = make_float2(hn0, hn2);
                *(float2*)&out[it + 338] = make_float2(hn1, hn3);
            }
        }
    }
}

// ---------------------------------------------------------------------------
extern "C" void kernel_launch(void* const* d_in, const int* in_sizes, int n_in,
                              void* d_out, int out_size)
{
    const float* x        = (const float*)d_in[0];
    const float* deconv_w = (const float*)d_in[1];
    const float* deconv_b = (const float*)d_in[2];
    const float* pre_w    = (const float*)d_in[3];
    const float* pre_b    = (const float*)d_in[4];
    const float* u1_w     = (const float*)d_in[5];
    const float* u1_b     = (const float*)d_in[6];
    const float* u2_w     = (const float*)d_in[7];
    const float* u2_b     = (const float*)d_in[8];
    const float* w_inh    = (const float*)d_in[9];
    const float* w_exc    = (const float*)d_in[10];
    const float* alpha    = (const float*)d_in[11];
    const float* mu       = (const float*)d_in[12];
    float* out = (float*)d_out;

    const int smemC  = 2*CHUNK*PTILE*8 + 2*640*8;        // 53760+10240 = 64,000 B
    const int smemG1 = 2*CHUNK*ITILE*8 + 2*128*8;        // 45,312 B
    const int smemG2 = 2*CHUNK*PTILE*8 + 2*128*8;        // 55,808 B
    cudaFuncSetAttribute(k_conv<C0,0>, cudaFuncAttributeMaxDynamicSharedMemorySize, smemC);
    cudaFuncSetAttribute(k_conv<M, 1>, cudaFuncAttributeMaxDynamicSharedMemorySize, smemC);
    cudaFuncSetAttribute(k_conv<M, 2>, cudaFuncAttributeMaxDynamicSharedMemorySize, smemC);
    cudaFuncSetAttribute(k_conv<M, 3>, cudaFuncAttributeMaxDynamicSharedMemorySize, smemC);
    cudaFuncSetAttribute(k_gatec<0>,   cudaFuncAttributeMaxDynamicSharedMemorySize, smemG1);
    cudaFuncSetAttribute(k_gatec<1>,   cudaFuncAttributeMaxDynamicSharedMemorySize, smemG2);

    // Weight prep (tiny; destinations resolved device-side)
    k_wprep_conv<0><<<(10*32*640 + 255)/256, 256>>>(pre_w, 32, 256, 10*32*640);
    k_wprep_conv<1><<<(10*10*640 + 255)/256, 256>>>(w_inh, 10, 80, 10*10*640);
    k_wprep_conv<2><<<(10*10*640 + 255)/256, 256>>>(w_exc, 10, 80, 10*10*640);
    k_wprep_gate<0><<<(6400 + 255)/256, 256>>>(u1_w);
    k_wprep_gate<1><<<(6400 + 255)/256, 256>>>(u2_w);

    // Feedforward (preproc also writes h2=0 and ns2=softplus(xp) — fused init)
    k_deconv<<<dim3(25, NB), 256>>>(x, (const float4*)deconv_w, deconv_b);
    k_conv<C0,0><<<dim3(10, NB), 192, smemC>>>(pre_b, nullptr, nullptr);

    // t = 0 (h == 0 -> hg == 0 -> c1 == 0 -> ns1 = softplus(xp))
    k_gatec<1><<<dim3(5, NB), 192, smemG2>>>(u2_b);
    k_conv<M,2><<<dim3(10, NB), 192, smemC>>>(nullptr, nullptr, nullptr);

    // t = 1 .. 9
    for (int t = 1; t < 10; t++) {
        k_gatec<0><<<dim3(5, NB), 192, smemG1>>>(u1_b);
        k_conv<M,1><<<dim3(10, NB), 192, smemC>>>(alpha, mu, nullptr);
        k_gatec<1><<<dim3(5, NB), 192, smemG2>>>(u2_b);
        if (t < 9)
            k_conv<M,2><<<dim3(10, NB), 192, smemC>>>(nullptr, nullptr, nullptr);
        else
            k_conv<M,3><<<dim3(10, NB), 192, smemC>>>(nullptr, nullptr, out);
    }
}

// round 16
// speedup vs baseline: 1.0870x; 1.0870x over previous
#include <cuda_runtime.h>
#include <math.h>
#include <stdint.h>

#define NB   512
#define C0   256
#define M    80
#define PIX  676      // 26*26
#define CHUNK 16
#define PTILE 420     // 15 packed rows * 28 cols (padded pair entries per channel)
#define ITILE 338     // 13 * 26 interior pair entries per channel

typedef unsigned long long ull;

// Data tensors (packed-pair layouts)
__device__ float2 g_y2 [512u*256u*420u];       // deconv out, padded-pair layout
__device__ float2 g_xp2[512u*80u*338u];        // preproc "x", interior pairs
__device__ float2 g_h2 [512u*80u*338u];        // hidden state, interior pairs
__device__ float2 g_g2p[512u*80u*338u];        // sigmoid(u2.ns1+b2), interior pairs
__device__ ulonglong2 g_hg2[512u*80u*210u];    // h*g1, padded pairs [15][28]
__device__ ulonglong2 g_ns2[512u*80u*210u];    // ns1,  padded pairs [15][28]

// Pre-duplicated weights — accessed ONLY from device code (never passed from host)
__device__ ull g_wpre[10u*16u*1280u];          // preproc  (MT=10, NCH=16)
__device__ ull g_winh[10u*5u*1280u];           // w_inh    (MT=10, NCH=5)
__device__ ull g_wexc[10u*5u*1280u];           // w_exc
__device__ ull g_wu1 [5u*5u*256u];             // u1 gate  (MT=5, NCH=5, 16ml x 16c)
__device__ ull g_wu2 [5u*5u*256u];             // u2 gate

__device__ __forceinline__ float sigm_(float v) { return 1.f / (1.f + expf(-v)); }
__device__ __forceinline__ float sftp_(float v) { return fmaxf(v, 0.f) + log1pf(expf(-fabsf(v))); }

__device__ __forceinline__ ull pk2(float lo, float hi) {
    ull r; asm("mov.b64 %0, {%1, %2};" : "=l"(r) : "f"(lo), "f"(hi)); return r;
}
__device__ __forceinline__ void upk2(ull v, float& lo, float& hi) {
    asm("mov.b64 {%0, %1}, %2;" : "=f"(lo), "=f"(hi) : "l"(v));
}
__device__ __forceinline__ ull fma2(ull a, ull b, ull c) {
    ull d; asm("fma.rn.f32x2 %0, %1, %2, %3;" : "=l"(d) : "l"(a), "l"(b), "l"(c)); return d;
}
__device__ __forceinline__ void cpa16(void* s, const void* g) {
    uint32_t sa = (uint32_t)__cvta_generic_to_shared(s);
    asm volatile("cp.async.cg.shared.global [%0], [%1], 16;" :: "r"(sa), "l"(g));
}
__device__ __forceinline__ void cpa_wait() {
    asm volatile("cp.async.commit_group;" ::: "memory");
    asm volatile("cp.async.wait_group 0;" ::: "memory");
}

// ---------------------------------------------------------------------------
// Weight prep kernels. SEL chooses the DEVICE-side destination buffer.
// Conv layout per (mt,ch): [(ml*16 + c)*10 + slot], slot 9 zero.
// Gate layout per (mt,ch): [ml*16 + c].
// ---------------------------------------------------------------------------
template<int SEL>   // 0 = preproc, 1 = inh, 2 = exc
__global__ void k_wprep_conv(const float* __restrict__ w, int NCH, int CIN, int total)
{
    ull* dst = (SEL == 0) ? g_wpre : (SEL == 1) ? g_winh : g_wexc;
    int idx = blockIdx.x*256 + threadIdx.x;
    if (idx >= total) return;
    int slot = idx % 10; int q = idx / 10;
    int c = q % 16; q /= 16;
    int ml = q % 8; q /= 8;
    int ch = q % NCH; int mt = q / NCH;
    ull v = 0ull;
    if (slot < 9) {
        float wv = w[((mt*8 + ml)*CIN + ch*16 + c)*9 + slot];
        v = pk2(wv, wv);
    }
    dst[idx] = v;
}

template<int G>     // 0 = u1, 1 = u2
__global__ void k_wprep_gate(const float* __restrict__ uw)
{
    ull* dst = G ? g_wu2 : g_wu1;
    int idx = blockIdx.x*256 + threadIdx.x;
    if (idx >= 5*5*256) return;
    int c = idx % 16; int q = idx / 16;
    int ml = q % 16; q /= 16;
    int ch = q % 5; int mt = q / 5;
    float wv = uw[(mt*16 + ml)*M + ch*16 + c];
    dst[idx] = pk2(wv, wv);
}

// ---------------------------------------------------------------------------
// Deconv 2x2 / stride 2; writes packed-pair layout g_y2 (rows 13/14 dup'd).
// ---------------------------------------------------------------------------
__global__ __launch_bounds__(256) void k_deconv(const float* __restrict__ x,
                                                const float4* __restrict__ dw4,
                                                const float* __restrict__ db)
{
    __shared__ ull xs[8][256];
    const int n = blockIdx.y;
    const int pid0 = blockIdx.x * 8;
    const int tid = threadIdx.x;

    #pragma unroll
    for (int g = 0; g < 8; g++) {
        int pid = pid0 + g;
        float v = (pid < 196) ? x[(n*256 + tid)*196 + pid] : 0.f;
        xs[g][tid] = pk2(v, v);
    }
    __syncthreads();

    ull acc0[8], acc1[8];
    #pragma unroll
    for (int g = 0; g < 8; g++) { acc0[g] = 0ull; acc1[g] = 0ull; }

    for (int ch = 0; ch < 256; ch++) {
        float4 w = dw4[ch*256 + tid];
        ull w01 = pk2(w.x, w.y);
        ull w23 = pk2(w.z, w.w);
        #pragma unroll
        for (int g = 0; g < 8; g++) {
            ull xv = xs[g][ch];
            acc0[g] = fma2(xv, w01, acc0[g]);
            acc1[g] = fma2(xv, w23, acc1[g]);
        }
    }

    const float b = db[tid];
    float2* yc = g_y2 + (ull)(n*256 + tid)*PTILE;
    #pragma unroll
    for (int g = 0; g < 8; g++) {
        int pid = pid0 + g;
        if (pid < 196) {
            int i = pid / 14, j = pid % 14;
            float a0,a1,a2,a3; upk2(acc0[g],a0,a1); upk2(acc1[g],a2,a3);
            a0 += b; a1 += b; a2 += b; a3 += b;
            int ry0 = 2*i, ry1 = 2*i + 1, col0 = 2*j, col1 = 2*j + 1;
            if (ry0 <= 14) {
                ((float*)&yc[ry0*28 + col0])[0] = a0;
                ((float*)&yc[ry0*28 + col1])[0] = a1;
            }
            if (ry0 >= 13) {
                ((float*)&yc[(ry0-13)*28 + col0])[1] = a0;
                ((float*)&yc[(ry0-13)*28 + col1])[1] = a1;
            }
            if (ry1 <= 14) {
                ((float*)&yc[ry1*28 + col0])[0] = a2;
                ((float*)&yc[ry1*28 + col1])[0] = a3;
            }
            if (ry1 >= 13) {
                ((float*)&yc[(ry1-13)*28 + col0])[1] = a2;
                ((float*)&yc[(ry1-13)*28 + col1])[1] = a3;
            }
        }
    }
}

// ---------------------------------------------------------------------------
// Blocked 1x1 gates, single-buffered cp.async staging.
// G=0: gate1 (src g_h2; out g_hg2 padded incl. dup halo).
// G=1: gate2 (src g_ns2 padded; out g_g2p interior).
// ---------------------------------------------------------------------------
template<int G>
__global__ __launch_bounds__(192, 3) void k_gatec(const float* __restrict__ ub)
{
    constexpr int IN = G ? PTILE : ITILE;   // float2 entries per channel
    constexpr int S2 = IN / 2;              // ulonglong2 per channel
    const ull* wp = G ? g_wu2 : g_wu1;
    extern __shared__ float sm[];
    float2* sIn = (float2*)sm;                     // CHUNK * IN
    ull*    sW  = (ull*)(sIn + CHUNK*IN);          // 256

    const int n = blockIdx.y, mt = blockIdx.x, tid = threadIdx.x;
    const bool act = tid < 169;
    const int py  = act ? tid / 13 : 0;
    const int px0 = act ? (tid % 13) * 2 : 0;
    const int e0  = py*26 + px0;
    const int ep  = (py+1)*28 + px0 + 1;

    const ulonglong2* srcBase = G
        ? (const ulonglong2*)((const float2*)g_ns2 + (ull)(n*M)*PTILE)
        : (const ulonglong2*)(g_h2 + (ull)(n*M)*ITILE);

    ull acc[16][2];
    #pragma unroll
    for (int ml = 0; ml < 16; ml++) { acc[ml][0] = 0ull; acc[ml][1] = 0ull; }

    for (int ch = 0; ch < 5; ch++) {
        __syncthreads();
        {
            const ulonglong2* src = srcBase + (ull)ch*CHUNK*S2;
            ulonglong2* di = (ulonglong2*)sIn;
            for (int idx = tid; idx < CHUNK*S2; idx += 192) cpa16(di + idx, src + idx);
            const ulonglong2* ws = (const ulonglong2*)(wp + (ull)(mt*5 + ch)*256);
            ulonglong2* dw = (ulonglong2*)sW;
            if (tid < 128) cpa16(dw + tid, ws + tid);
        }
        cpa_wait();
        __syncthreads();

        #pragma unroll 1
        for (int c = 0; c < CHUNK; c++) {
            ull P0, P1;
            if (G) {
                const ull* s = (const ull*)(sIn + c*PTILE + ep);
                P0 = s[0]; P1 = s[1];
            } else {
                ulonglong2 v = *(const ulonglong2*)(sIn + c*ITILE + e0);
                P0 = v.x; P1 = v.y;
            }
            #pragma unroll
            for (int ml = 0; ml < 16; ml++) {
                ull wv = sW[ml*CHUNK + c];
                acc[ml][0] = fma2(P0, wv, acc[ml][0]);
                acc[ml][1] = fma2(P1, wv, acc[ml][1]);
            }
        }
    }

    if (!act) return;

    #pragma unroll
    for (int ml = 0; ml < 16; ml++) {
        const int m = mt*16 + ml;
        const float b = ub[m];
        float t0,b0,t1,b1;
        upk2(acc[ml][0], t0, b0);
        upk2(acc[ml][1], t1, b1);
        if (G) {
            *(float4*)(g_g2p + (ull)(n*M + m)*ITILE + e0) =
                make_float4(sigm_(t0+b), sigm_(b0+b), sigm_(t1+b), sigm_(b1+b));
        } else {
            float4 hv = *(const float4*)(g_h2 + (ull)(n*M + m)*ITILE + e0);
            float vt0 = hv.x * sigm_(t0+b);
            float vb0 = hv.y * sigm_(b0+b);
            float vt1 = hv.z * sigm_(t1+b);
            float vb1 = hv.w * sigm_(b1+b);
            float2* chan = (float2*)g_hg2 + (ull)(n*M + m)*PTILE;
            float2* dst = chan + ep;
            dst[0] = make_float2(vt0, vb0);
            dst[1] = make_float2(vt1, vb1);
            if (py == 12) {                         // img row 12 -> (0,col).y
                ((float*)(chan + px0+1))[1] = vt0;
                ((float*)(chan + px0+2))[1] = vt1;
            }
            if (py == 0) {                          // img row 13 -> (14,col).x
                ((float*)(chan + 14*28 + px0+1))[0] = vb0;
                ((float*)(chan + 14*28 + px0+2))[0] = vb1;
            }
        }
    }
}

// ---------------------------------------------------------------------------
// Unified 3x3 conv, single-buffered staging, c-loop unroll 2.
//   EPI 0: preproc (src g_y2 packed; out g_xp2 + bias, g_h2 = 0,
//                   g_ns2 = softplus incl. dup halo -- fused t=0 init)
//   EPI 1: inh     (src g_hg2; out g_ns2 padded incl. dup halo)
//   EPI 2: exc -> g_h2  (GRU blend with g_g2p)
//   EPI 3: exc -> out (unpacked)
// ---------------------------------------------------------------------------
template<int CIN, int EPI>
__global__ __launch_bounds__(192, 3) void k_conv(const float* __restrict__ p0,
                                                 const float* __restrict__ p1,
                                                 float* __restrict__ out)
{
    constexpr int NCH = CIN / CHUNK;
    const ull* wp = (EPI == 0) ? g_wpre : (EPI == 1) ? g_winh : g_wexc;
    extern __shared__ float sm[];
    float2* sIn2 = (float2*)sm;                        // CHUNK*PTILE
    ull*    sWp  = (ull*)(sIn2 + CHUNK*PTILE);         // 1280

    const int n = blockIdx.y, mt = blockIdx.x, tid = threadIdx.x;
    const bool act = tid < 169;
    const int py  = act ? tid / 13 : 0;
    const int px0 = act ? (tid % 13) * 2 : 0;
    const int e0  = py*26 + px0;

    const ulonglong2* srcBase;
    if (EPI == 0)      srcBase = (const ulonglong2*)(g_y2 + (ull)(n*C0)*PTILE);
    else if (EPI == 1) srcBase = (const ulonglong2*)((const float2*)g_hg2 + (ull)(n*M)*PTILE);
    else               srcBase = (const ulonglong2*)((const float2*)g_ns2 + (ull)(n*M)*PTILE);

    ull acc[8][2];
    #pragma unroll
    for (int ml = 0; ml < 8; ml++) { acc[ml][0]=0ull; acc[ml][1]=0ull; }

    for (int ch = 0; ch < NCH; ch++) {
        __syncthreads();
        {
            const ulonglong2* src = srcBase + (ull)ch*CHUNK*210;
            ulonglong2* di = (ulonglong2*)sIn2;
            for (int idx = tid; idx < CHUNK*210; idx += 192) cpa16(di + idx, src + idx);
            const ulonglong2* ws = (const ulonglong2*)(wp + (ull)(mt*NCH + ch)*1280);
            ulonglong2* dw = (ulonglong2*)sWp;
            for (int idx = tid; idx < 640; idx += 192) cpa16(dw + idx, ws + idx);
        }
        cpa_wait();
        __syncthreads();

        #pragma unroll 2
        for (int c = 0; c < CHUNK; c++) {
            ull P[3][4];
            const float2* base = sIn2 + c*PTILE + py*28 + px0;
            #pragma unroll
            for (int r = 0; r < 3; r++) {
                const ulonglong2* rp = (const ulonglong2*)(base + r*28);
                ulonglong2 A = rp[0], B = rp[1];
                P[r][0] = A.x; P[r][1] = A.y; P[r][2] = B.x; P[r][3] = B.y;
            }
            #pragma unroll
            for (int ml = 0; ml < 8; ml++) {
                const ulonglong2* wp2 = (const ulonglong2*)(sWp + (ml*CHUNK + c)*10);
                ulonglong2 W01 = wp2[0], W23 = wp2[1];
                acc[ml][0] = fma2(P[0][0], W01.x, acc[ml][0]);
                acc[ml][1] = fma2(P[0][1], W01.x, acc[ml][1]);
                acc[ml][0] = fma2(P[0][1], W01.y, acc[ml][0]);
                acc[ml][1] = fma2(P[0][2], W01.y, acc[ml][1]);
                acc[ml][0] = fma2(P[0][2], W23.x, acc[ml][0]);
                acc[ml][1] = fma2(P[0][3], W23.x, acc[ml][1]);
                acc[ml][0] = fma2(P[1][0], W23.y, acc[ml][0]);
                acc[ml][1] = fma2(P[1][1], W23.y, acc[ml][1]);
                ulonglong2 W45 = wp2[2], W67 = wp2[3];
                acc[ml][0] = fma2(P[1][1], W45.x, acc[ml][0]);
                acc[ml][1] = fma2(P[1][2], W45.x, acc[ml][1]);
                acc[ml][0] = fma2(P[1][2], W45.y, acc[ml][0]);
                acc[ml][1] = fma2(P[1][3], W45.y, acc[ml][1]);
                acc[ml][0] = fma2(P[2][0], W67.x, acc[ml][0]);
                acc[ml][1] = fma2(P[2][1], W67.x, acc[ml][1]);
                acc[ml][0] = fma2(P[2][1], W67.y, acc[ml][0]);
                acc[ml][1] = fma2(P[2][2], W67.y, acc[ml][1]);
                ull W8 = ((const ull*)wp2)[8];
                acc[ml][0] = fma2(P[2][2], W8, acc[ml][0]);
                acc[ml][1] = fma2(P[2][3], W8, acc[ml][1]);
            }
        }
    }

    if (!act) return;

    #pragma unroll
    for (int ml = 0; ml < 8; ml++) {
        const int m = mt*8 + ml;
        const ull b338 = (ull)(n*M + m)*ITILE;
        float t0,b0,t1,b1;
        upk2(acc[ml][0], t0, b0);
        upk2(acc[ml][1], t1, b1);

        if (EPI == 0) {
            float b = p0[m];
            float xt0 = t0+b, xb0 = b0+b, xt1 = t1+b, xb1 = b1+b;
            *(float4*)(g_xp2 + b338 + e0) = make_float4(xt0, xb0, xt1, xb1);
            *(float4*)(g_h2  + b338 + e0) = make_float4(0.f, 0.f, 0.f, 0.f);
            float nt0 = sftp_(xt0), nb0 = sftp_(xb0), nt1 = sftp_(xt1), nb1 = sftp_(xb1);
            float2* chan = (float2*)g_ns2 + (ull)(n*M + m)*PTILE;
            float2* dst = chan + (py+1)*28 + px0 + 1;
            dst[0] = make_float2(nt0, nb0);
            dst[1] = make_float2(nt1, nb1);
            if (py == 12) {                         // img row 12 -> (0,col).y
                ((float*)(chan + px0+1))[1] = nt0;
                ((float*)(chan + px0+2))[1] = nt1;
            }
            if (py == 0) {                          // img row 13 -> (14,col).x
                ((float*)(chan + 14*28 + px0+1))[0] = nb0;
                ((float*)(chan + 14*28 + px0+2))[0] = nb1;
            }
        } else if (EPI == 1) {
            float al = p0[m], mm = p1[m];
            float4 xv = *(const float4*)(g_xp2 + b338 + e0);
            float4 hv = *(const float4*)(g_h2  + b338 + e0);
            float nt0 = sftp_(xv.x - t0*(al*hv.x + mm));
            float nb0 = sftp_(xv.y - b0*(al*hv.y + mm));
            float nt1 = sftp_(xv.z - t1*(al*hv.z + mm));
            float nb1 = sftp_(xv.w - b1*(al*hv.w + mm));
            float2* chan = (float2*)g_ns2 + (ull)(n*M + m)*PTILE;
            float2* dst = chan + (py+1)*28 + px0 + 1;
            dst[0] = make_float2(nt0, nb0);
            dst[1] = make_float2(nt1, nb1);
            if (py == 12) {                         // img row 12 -> (0,col).y
                ((float*)(chan + px0+1))[1] = nt0;
                ((float*)(chan + px0+2))[1] = nt1;
            }
            if (py == 0) {                          // img row 13 -> (14,col).x
                ((float*)(chan + 14*28 + px0+1))[0] = nb0;
                ((float*)(chan + 14*28 + px0+2))[0] = nb1;
            }
        } else {
            float4 gv = *(const float4*)(g_g2p + b338 + e0);
            float4 hv = *(const float4*)(g_h2  + b338 + e0);
            float hn0 = (1.f - gv.x)*hv.x + gv.x*sftp_(t0);
            float hn1 = (1.f - gv.y)*hv.y + gv.y*sftp_(b0);
            float hn2 = (1.f - gv.z)*hv.z + gv.z*sftp_(t1);
            float hn3 = (1.f - gv.w)*hv.w + gv.w*sftp_(b1);
            if (EPI == 2) {
                *(float4*)(g_h2 + b338 + e0) = make_float4(hn0, hn1, hn2, hn3);
            } else {
                const int it = (n*M + m)*PIX + e0;
                *(float2*)&out[it]       = make_float2(hn0, hn2);
                *(float2*)&out[it + 338] = make_float2(hn1, hn3);
            }
        }
    }
}

// ---------------------------------------------------------------------------
extern "C" void kernel_launch(void* const* d_in, const int* in_sizes, int n_in,
                              void* d_out, int out_size)
{
    const float* x        = (const float*)d_in[0];
    const float* deconv_w = (const float*)d_in[1];
    const float* deconv_b = (const float*)d_in[2];
    const float* pre_w    = (const float*)d_in[3];
    const float* pre_b    = (const float*)d_in[4];
    const float* u1_w     = (const float*)d_in[5];
    const float* u1_b     = (const float*)d_in[6];
    const float* u2_w     = (const float*)d_in[7];
    const float* u2_b     = (const float*)d_in[8];
    const float* w_inh    = (const float*)d_in[9];
    const float* w_exc    = (const float*)d_in[10];
    const float* alpha    = (const float*)d_in[11];
    const float* mu       = (const float*)d_in[12];
    float* out = (float*)d_out;

    const int smemC  = CHUNK*PTILE*8 + 1280*8;           // 64,000 B
    const int smemG1 = CHUNK*ITILE*8 + 256*8;            // 45,312 B
    const int smemG2 = CHUNK*PTILE*8 + 256*8;            // 55,808 B
    cudaFuncSetAttribute(k_conv<C0,0>, cudaFuncAttributeMaxDynamicSharedMemorySize, smemC);
    cudaFuncSetAttribute(k_conv<M, 1>, cudaFuncAttributeMaxDynamicSharedMemorySize, smemC);
    cudaFuncSetAttribute(k_conv<M, 2>, cudaFuncAttributeMaxDynamicSharedMemorySize, smemC);
    cudaFuncSetAttribute(k_conv<M, 3>, cudaFuncAttributeMaxDynamicSharedMemorySize, smemC);
    cudaFuncSetAttribute(k_gatec<0>,   cudaFuncAttributeMaxDynamicSharedMemorySize, smemG1);
    cudaFuncSetAttribute(k_gatec<1>,   cudaFuncAttributeMaxDynamicSharedMemorySize, smemG2);

    // Launch order arranged so index 3 (the ncu-captured slot) is k_conv<C0,0>.
    k_wprep_gate<1><<<(6400 + 255)/256, 256>>>(u2_w);                      // [0]
    k_wprep_conv<0><<<(10*16*1280 + 255)/256, 256>>>(pre_w, 16, 256, 10*16*1280); // [1]
    k_deconv<<<dim3(25, NB), 256>>>(x, (const float4*)deconv_w, deconv_b); // [2]
    k_conv<C0,0><<<dim3(10, NB), 192, smemC>>>(pre_b, nullptr, nullptr);   // [3] <- profiled

    // Remaining weight prep (before their first consumers)
    k_wprep_conv<1><<<(10*5*1280 + 255)/256, 256>>>(w_inh, 5, 80, 10*5*1280);
    k_wprep_conv<2><<<(10*5*1280 + 255)/256, 256>>>(w_exc, 5, 80, 10*5*1280);
    k_wprep_gate<0><<<(6400 + 255)/256, 256>>>(u1_w);

    // t = 0 (h == 0 -> hg == 0 -> c1 == 0 -> ns1 = softplus(xp))
    k_gatec<1><<<dim3(5, NB), 192, smemG2>>>(u2_b);
    k_conv<M,2><<<dim3(10, NB), 192, smemC>>>(nullptr, nullptr, nullptr);

    // t = 1 .. 9
    for (int t = 1; t < 10; t++) {
        k_gatec<0><<<dim3(5, NB), 192, smemG1>>>(u1_b);
        k_conv<M,1><<<dim3(10, NB), 192, smemC>>>(alpha, mu, nullptr);
        k_gatec<1><<<dim3(5, NB), 192, smemG2>>>(u2_b);
        if (t < 9)
            k_conv<M,2><<<dim3(10, NB), 192, smemC>>>(nullptr, nullptr, nullptr);
        else
            k_conv<M,3><<<dim3(10, NB), 192, smemC>>>(nullptr, nullptr, out);
    }
}